// round 6
// baseline (speedup 1.0000x reference)
#include <cuda_runtime.h>
#include <cuda_bf16.h>
#include <cstdint>

#define N_NODES  50000
#define N_EDGES  800000
#define N_GRAPHS 512
#define IN_C     128
#define HID      256
#define OUT_C    16

// ---------------- scratch (static device globals; no allocation) -------------
__device__ float g_agg [(size_t)N_NODES * HID];
__device__ float g_tmp [(size_t)N_NODES * HID];
__device__ float g_h   [(size_t)N_NODES * HID];
__device__ float g_pool[N_GRAPHS * HID];
__device__ int   g_deg   [N_NODES];
__device__ int   g_rowptr[N_NODES + 1];
__device__ int   g_cursor[N_NODES];
__device__ int   g_csr   [N_EDGES];
__device__ int   g_gstart[N_GRAPHS + 1];
__device__ int   g_bprefix[128];
__device__ int   g_bflag  [128];

// ---------------- inline int32/int64 index-width autodetect -------------------
// edge_index values are random in [0, 50000). If int64 (LE), odd 32-bit words
// of the first entries are all zero; if int32 they are random indices.
__device__ __forceinline__ int detect64(const void* ei) {
    const unsigned int* w = (const unsigned int*)ei;
    return ((w[1] | w[3] | w[5] | w[7]) == 0u) ? 1 : 0;
}
__device__ __forceinline__ int idx_at(const void* p, long long i, int is64) {
    if (is64) return (int)((const long long*)p)[i];
    return ((const int*)p)[i];
}

// ---------------- CSR build ----------------------------------------------------
__global__ void deg_hist(const void* __restrict__ ei, int* __restrict__ deg) {
    int is64 = detect64(ei);
    int e = blockIdx.x * blockDim.x + threadIdx.x;
    if (e >= N_EDGES) return;
    int d = idx_at(ei, (long long)N_EDGES + e, is64);
    atomicAdd(&deg[d], 1);
}

// single-kernel chained scan (98 blocks, all resident -> spin is safe).
// g_bflag must be zeroed before launch (cudaMemsetAsync in launcher).
#define SCAN_B 512
__global__ void scan_fused(const int* __restrict__ deg,
                           int* __restrict__ rowptr,
                           int* __restrict__ cursor) {
    __shared__ int s[SCAN_B];
    __shared__ int prefix_sh;
    int b = blockIdx.x, t = threadIdx.x;
    int i = b * SCAN_B + t;
    int v = (i < N_NODES) ? deg[i] : 0;
    s[t] = v; __syncthreads();
    for (int off = 1; off < SCAN_B; off <<= 1) {
        int x = (t >= off) ? s[t - off] : 0;
        __syncthreads();
        s[t] += x;
        __syncthreads();
    }
    if (t == 0) {
        int p = 0;
        if (b > 0) {
            while (atomicAdd(&g_bflag[b - 1], 0) == 0) {}
            p = atomicAdd(&g_bprefix[b - 1], 0);
        }
        prefix_sh = p;
        g_bprefix[b] = p + s[SCAN_B - 1];
        __threadfence();
        atomicExch(&g_bflag[b], 1);
    }
    __syncthreads();
    if (i < N_NODES) {
        int ex = prefix_sh + s[t] - v;
        rowptr[i] = ex;
        cursor[i] = ex;
    }
    if (b == 0 && t == 0) rowptr[N_NODES] = N_EDGES;
}

__global__ void csr_fill(const void* __restrict__ ei, int* __restrict__ cursor,
                         int* __restrict__ csr) {
    int is64 = detect64(ei);
    int e = blockIdx.x * blockDim.x + threadIdx.x;
    if (e >= N_EDGES) return;
    int s = idx_at(ei, e, is64);
    int d = idx_at(ei, (long long)N_EDGES + e, is64);
    int p = atomicAdd(&cursor[d], 1);
    csr[p] = s;
}

// ---------------- aggregation: out[i] = h[i] + sum_{j in N(i)} h[j] ----------
// float4 lanes; C4 = C/4 threads per node; 8-deep edge unroll for MLP.
__global__ void aggregate4(const float4* __restrict__ h4,
                           const int* __restrict__ rowptr,
                           const int* __restrict__ csr,
                           float4* __restrict__ out,
                           int c4shift)            // log2(C/4): 5 or 6
{
    int c4 = 1 << c4shift;
    int sub  = threadIdx.x >> c4shift;
    int t    = threadIdx.x & (c4 - 1);
    int npb  = 256 >> c4shift;
    int node = blockIdx.x * npb + sub;
    if (node >= N_NODES) return;

    int beg = rowptr[node], end = rowptr[node + 1];
    float4 acc = h4[((size_t)node << c4shift) + t];
    int e = beg;
    for (; e + 8 <= end; e += 8) {
        int si[8];
        #pragma unroll
        for (int j = 0; j < 8; j++) si[j] = csr[e + j];
        float4 v[8];
        #pragma unroll
        for (int j = 0; j < 8; j++)
            v[j] = h4[((size_t)si[j] << c4shift) + t];
        #pragma unroll
        for (int j = 0; j < 8; j++) {
            acc.x += v[j].x; acc.y += v[j].y;
            acc.z += v[j].z; acc.w += v[j].w;
        }
    }
    for (; e + 4 <= end; e += 4) {
        int s0 = csr[e], s1 = csr[e + 1], s2 = csr[e + 2], s3 = csr[e + 3];
        float4 v0 = h4[((size_t)s0 << c4shift) + t];
        float4 v1 = h4[((size_t)s1 << c4shift) + t];
        float4 v2 = h4[((size_t)s2 << c4shift) + t];
        float4 v3 = h4[((size_t)s3 << c4shift) + t];
        acc.x += v0.x + v1.x + v2.x + v3.x;
        acc.y += v0.y + v1.y + v2.y + v3.y;
        acc.z += v0.z + v1.z + v2.z + v3.z;
        acc.w += v0.w + v1.w + v2.w + v3.w;
    }
    for (; e < end; e++) {
        float4 v = h4[((size_t)csr[e] << c4shift) + t];
        acc.x += v.x; acc.y += v.y; acc.z += v.z; acc.w += v.w;
    }
    out[((size_t)node << c4shift) + t] = acc;
}

// ---------------- TF32 tensor-core GEMM: C = relu(A @ W + bias) ---------------
#define GBM 128
#define GBN 128
#define GBK 32
#define ASTRIDE 36
#define BSTRIDE 136

__device__ __forceinline__ uint32_t f2tf32(float f) {
    uint32_t r;
    asm("cvt.rna.tf32.f32 %0, %1;" : "=r"(r) : "f"(f));
    return r;
}

__global__ __launch_bounds__(256, 2)
void gemm_tf32(const float* __restrict__ A,
               const float* __restrict__ W,      // K x N row-major
               const float* __restrict__ bias,   // N
               float* __restrict__ C,
               int M, int K, int N)
{
    __shared__ uint32_t As[GBM][ASTRIDE];
    __shared__ uint32_t Bs[GBK][BSTRIDE];

    int bm = blockIdx.x * GBM;
    int bn = blockIdx.y * GBN;
    int tid  = threadIdx.x;
    int wid  = tid >> 5;
    int lane = tid & 31;
    int grp  = lane >> 2;     // 0..7
    int tig  = lane & 3;      // 0..3
    int wm = (wid & 3) * 32;  // warp row offset in tile
    int wn = (wid >> 2) * 64; // warp col offset in tile

    float acc[2][8][4];
    #pragma unroll
    for (int i = 0; i < 2; i++)
        #pragma unroll
        for (int j = 0; j < 8; j++)
            #pragma unroll
            for (int r = 0; r < 4; r++) acc[i][j][r] = 0.f;

    float4 pa[4], pb[4];

    auto ld_tiles = [&](int k0) {
        #pragma unroll
        for (int i = 0; i < 4; i++) {
            int li = tid + i * 256;
            int r  = li >> 3;          // 0..127
            int cq = (li & 7) * 4;     // 0..28
            int row = bm + r;
            pa[i] = (row < M) ? *(const float4*)(A + (size_t)row * K + k0 + cq)
                              : make_float4(0.f, 0.f, 0.f, 0.f);
        }
        #pragma unroll
        for (int i = 0; i < 4; i++) {
            int li = tid + i * 256;
            int kr = li >> 5;          // 0..31
            int cq = (li & 31) * 4;    // 0..124
            pb[i] = *(const float4*)(W + (size_t)(k0 + kr) * N + bn + cq);
        }
    };

    auto st_tiles = [&]() {
        #pragma unroll
        for (int i = 0; i < 4; i++) {
            int li = tid + i * 256;
            int r  = li >> 3;
            int cq = (li & 7) * 4;
            As[r][cq + 0] = f2tf32(pa[i].x);
            As[r][cq + 1] = f2tf32(pa[i].y);
            As[r][cq + 2] = f2tf32(pa[i].z);
            As[r][cq + 3] = f2tf32(pa[i].w);
        }
        #pragma unroll
        for (int i = 0; i < 4; i++) {
            int li = tid + i * 256;
            int kr = li >> 5;
            int cq = (li & 31) * 4;
            Bs[kr][cq + 0] = f2tf32(pb[i].x);
            Bs[kr][cq + 1] = f2tf32(pb[i].y);
            Bs[kr][cq + 2] = f2tf32(pb[i].z);
            Bs[kr][cq + 3] = f2tf32(pb[i].w);
        }
    };

    ld_tiles(0);

    for (int k0 = 0; k0 < K; k0 += GBK) {
        st_tiles();
        __syncthreads();
        if (k0 + GBK < K) ld_tiles(k0 + GBK);   // hide LDG behind MMA phase

        #pragma unroll
        for (int ks = 0; ks < GBK; ks += 8) {
            uint32_t af[2][4];
            #pragma unroll
            for (int mt = 0; mt < 2; mt++) {
                int r0 = wm + mt * 16 + grp;
                af[mt][0] = As[r0][ks + tig];
                af[mt][1] = As[r0 + 8][ks + tig];
                af[mt][2] = As[r0][ks + tig + 4];
                af[mt][3] = As[r0 + 8][ks + tig + 4];
            }
            uint32_t bf[8][2];
            #pragma unroll
            for (int nt = 0; nt < 8; nt++) {
                int c0 = wn + nt * 8 + grp;
                bf[nt][0] = Bs[ks + tig][c0];
                bf[nt][1] = Bs[ks + tig + 4][c0];
            }
            #pragma unroll
            for (int mt = 0; mt < 2; mt++)
                #pragma unroll
                for (int nt = 0; nt < 8; nt++) {
                    asm volatile(
                        "mma.sync.aligned.m16n8k8.row.col.f32.tf32.tf32.f32 "
                        "{%0,%1,%2,%3}, {%4,%5,%6,%7}, {%8,%9}, {%0,%1,%2,%3};"
                        : "+f"(acc[mt][nt][0]), "+f"(acc[mt][nt][1]),
                          "+f"(acc[mt][nt][2]), "+f"(acc[mt][nt][3])
                        : "r"(af[mt][0]), "r"(af[mt][1]),
                          "r"(af[mt][2]), "r"(af[mt][3]),
                          "r"(bf[nt][0]), "r"(bf[nt][1]));
                }
        }
        __syncthreads();
    }

    // epilogue: bias + relu, float2 stores
    #pragma unroll
    for (int mt = 0; mt < 2; mt++) {
        #pragma unroll
        for (int nt = 0; nt < 8; nt++) {
            int col = bn + wn + nt * 8 + 2 * tig;
            float b0 = bias[col], b1 = bias[col + 1];
            int r0 = bm + wm + mt * 16 + grp;
            if (r0 < M) {
                float2 c;
                c.x = fmaxf(acc[mt][nt][0] + b0, 0.f);
                c.y = fmaxf(acc[mt][nt][1] + b1, 0.f);
                *(float2*)(C + (size_t)r0 * N + col) = c;
            }
            if (r0 + 8 < M) {
                float2 c;
                c.x = fmaxf(acc[mt][nt][2] + b0, 0.f);
                c.y = fmaxf(acc[mt][nt][3] + b1, 0.f);
                *(float2*)(C + (size_t)(r0 + 8) * N + col) = c;
            }
        }
    }
}

// ---------------- pooling over sorted batch -----------------------------------
__global__ void graph_bounds(const void* __restrict__ batch,
                             const void* __restrict__ ei,
                             int* __restrict__ gstart) {
    int is64 = detect64(ei);
    int g = blockIdx.x * blockDim.x + threadIdx.x;
    if (g > N_GRAPHS) return;
    int lo = 0, hi = N_NODES;
    while (lo < hi) {
        int mid = (lo + hi) >> 1;
        if (idx_at(batch, mid, is64) < g) lo = mid + 1; else hi = mid;
    }
    gstart[g] = lo;
}

__global__ void pool_mean(const float* __restrict__ h,
                          const int* __restrict__ gstart,
                          float* __restrict__ pooled) {
    int g = blockIdx.x;
    int t = threadIdx.x;           // HID threads
    int beg = gstart[g], end = gstart[g + 1];
    float acc = 0.f;
    int n = beg;
    for (; n + 4 <= end; n += 4) {
        float a0 = h[(size_t)(n + 0) * HID + t];
        float a1 = h[(size_t)(n + 1) * HID + t];
        float a2 = h[(size_t)(n + 2) * HID + t];
        float a3 = h[(size_t)(n + 3) * HID + t];
        acc += a0 + a1 + a2 + a3;
    }
    for (; n < end; n++) acc += h[(size_t)n * HID + t];
    float c = fmaxf((float)(end - beg), 1.0f);
    pooled[(size_t)g * HID + t] = acc / c;
}

// ---------------- final MLP: out = relu(pooled@W1+b1)@W2+b2 ------------------
__global__ void final_mlp(const float* __restrict__ pooled,
                          const float* __restrict__ w1, const float* __restrict__ b1,
                          const float* __restrict__ w2, const float* __restrict__ b2,
                          float* __restrict__ out) {
    __shared__ float p[HID];
    __shared__ float hh[HID];
    int g = blockIdx.x;
    int t = threadIdx.x;

    p[t] = pooled[(size_t)g * HID + t];
    __syncthreads();

    float acc = b1[t];
    #pragma unroll 8
    for (int k = 0; k < HID; k++)
        acc += p[k] * w1[(size_t)k * HID + t];
    hh[t] = fmaxf(acc, 0.f);
    __syncthreads();

    int o  = t >> 4;
    int kk = t & 15;
    float s = 0.f;
    for (int k = kk; k < HID; k += 16)
        s += hh[k] * w2[(size_t)k * OUT_C + o];
    #pragma unroll
    for (int off = 8; off; off >>= 1)
        s += __shfl_xor_sync(0xffffffffu, s, off);
    if (kk == 0) out[(size_t)g * OUT_C + o] = s + b2[o];
}

// ---------------- launcher ----------------------------------------------------
extern "C" void kernel_launch(void* const* d_in, const int* in_sizes, int n_in,
                              void* d_out, int out_size)
{
    const float* x     = (const float*)d_in[0];
    const void*  ei    = d_in[1];
    const void*  batch = d_in[2];
    const float* w[16];
    for (int i = 0; i < 16; i++) w[i] = (const float*)d_in[3 + i];
    float* out = (float*)d_out;

    float *agg, *tmp, *h, *pool;
    int *deg, *rowptr, *cursor, *csr, *gstart, *bflag;
    cudaGetSymbolAddress((void**)&agg,    g_agg);
    cudaGetSymbolAddress((void**)&tmp,    g_tmp);
    cudaGetSymbolAddress((void**)&h,      g_h);
    cudaGetSymbolAddress((void**)&pool,   g_pool);
    cudaGetSymbolAddress((void**)&deg,    g_deg);
    cudaGetSymbolAddress((void**)&rowptr, g_rowptr);
    cudaGetSymbolAddress((void**)&cursor, g_cursor);
    cudaGetSymbolAddress((void**)&csr,    g_csr);
    cudaGetSymbolAddress((void**)&gstart, g_gstart);
    cudaGetSymbolAddress((void**)&bflag,  g_bflag);

    // ---- CSR build (once, reused by all 3 layers) ----
    cudaMemsetAsync(deg, 0, N_NODES * sizeof(int));
    cudaMemsetAsync(bflag, 0, sizeof(g_bflag));
    deg_hist<<<(N_EDGES + 255) / 256, 256>>>(ei, deg);              // launch 0
    int nb = (N_NODES + SCAN_B - 1) / SCAN_B;                       // 98 blocks
    scan_fused<<<nb, SCAN_B>>>(deg, rowptr, cursor);                // launch 1
    csr_fill<<<(N_EDGES + 255) / 256, 256>>>(ei, cursor, csr);      // launch 2

    // ---- 3 GIN layers ----
    for (int layer = 0; layer < 3; layer++) {
        const float* hin = (layer == 0) ? x : h;
        int K = (layer == 0) ? IN_C : HID;
        int c4shift = (layer == 0) ? 5 : 6;
        int npb = 256 >> c4shift;

        aggregate4<<<(N_NODES + npb - 1) / npb, 256>>>(             // launch 3 (L0)
            (const float4*)hin, rowptr, csr, (float4*)agg, c4shift);

        dim3 grid((N_NODES + GBM - 1) / GBM, HID / GBN);
        gemm_tf32<<<grid, 256>>>(agg, w[layer * 4 + 0], w[layer * 4 + 1],
                                 tmp, N_NODES, K, HID);
        gemm_tf32<<<grid, 256>>>(tmp, w[layer * 4 + 2], w[layer * 4 + 3],
                                 h, N_NODES, HID, HID);
    }

    // ---- pooling (batch is sorted) ----
    graph_bounds<<<3, 256>>>(batch, ei, gstart);
    pool_mean<<<N_GRAPHS, HID>>>(h, gstart, pool);

    final_mlp<<<N_GRAPHS, HID>>>(pool, w[12], w[13], w[14], w[15], out);
}

// round 7
// speedup vs baseline: 1.0961x; 1.0961x over previous
#include <cuda_runtime.h>
#include <cuda_bf16.h>
#include <cstdint>

#define N_NODES  50000
#define N_EDGES  800000
#define N_GRAPHS 512
#define IN_C     128
#define HID      256
#define OUT_C    16

// ---------------- scratch (static device globals; no allocation) -------------
__device__ float g_agg [(size_t)N_NODES * HID];
__device__ float g_tmp [(size_t)N_NODES * HID];
__device__ float g_h   [(size_t)N_NODES * HID];
__device__ float g_pool[N_GRAPHS * HID];
__device__ int   g_deg   [N_NODES];
__device__ int   g_rowptr[N_NODES + 1];
__device__ int   g_cursor[N_NODES];
__device__ int   g_csr   [N_EDGES];
__device__ int   g_gstart[N_GRAPHS + 1];
__device__ int   g_chain [128 * 32];   // flag slots padded to 128B
__device__ int   g_arrive;

// ---------------- inline int32/int64 index-width autodetect -------------------
// edge_index values are random in [0, 50000). If int64 (LE), odd 32-bit words
// are zero; if int32 they are random indices (prob of 4 zeros ~ 0).
__device__ __forceinline__ int detect64(const void* ei) {
    const unsigned int* w = (const unsigned int*)ei;
    return ((w[1] | w[3] | w[5] | w[7]) == 0u) ? 1 : 0;
}
__device__ __forceinline__ int idx_at(const void* p, long long i, int is64) {
    if (is64) return (int)((const long long*)p)[i];
    return ((const int*)p)[i];
}

// ---------------- fused CSR phase 1: histogram + grid barrier + scan ----------
// 98 blocks x 512 threads; grid < #SMs so all blocks are resident -> spin-safe.
// g_arrive and g_chain must be zeroed before launch (cudaMemsetAsync).
#define SCAN_B 512
#define SCAN_NB ((N_NODES + SCAN_B - 1) / SCAN_B)   // 98

__global__ __launch_bounds__(SCAN_B, 1)
void hist_scan(const void* __restrict__ ei,
               int* __restrict__ deg,
               int* __restrict__ rowptr,
               int* __restrict__ cursor) {
    int b = blockIdx.x, t = threadIdx.x;
    int is64 = detect64(ei);

    // --- phase 1: degree histogram (block-partitioned edges) ---
    int per = (N_EDGES + SCAN_NB - 1) / SCAN_NB;
    int ebeg = b * per;
    int eend = min(ebeg + per, N_EDGES);
    for (int e = ebeg + t; e < eend; e += SCAN_B) {
        int d = idx_at(ei, (long long)N_EDGES + e, is64);
        atomicAdd(&deg[d], 1);
    }

    // --- grid barrier (all 98 blocks resident) ---
    __syncthreads();
    if (t == 0) {
        __threadfence();
        atomicAdd(&g_arrive, 1);
        while (atomicAdd(&g_arrive, 0) < SCAN_NB) __nanosleep(64);
    }
    __syncthreads();

    // --- phase 2: block-local inclusive scan of this block's 512 degrees ---
    __shared__ int s[SCAN_B];
    __shared__ int prefix_sh;
    int i = b * SCAN_B + t;
    int v = (i < N_NODES) ? __ldcg(&deg[i]) : 0;
    s[t] = v; __syncthreads();
    for (int off = 1; off < SCAN_B; off <<= 1) {
        int x = (t >= off) ? s[t - off] : 0;
        __syncthreads();
        s[t] += x;
        __syncthreads();
    }

    // --- phase 3: chained cross-block prefix; flag value = prefix+1 ---
    if (t == 0) {
        int p = 0;
        if (b > 0) {
            int f;
            while ((f = atomicAdd(&g_chain[(b - 1) * 32], 0)) == 0)
                __nanosleep(32);
            p = f - 1;
        }
        prefix_sh = p;
        atomicExch(&g_chain[b * 32], p + s[SCAN_B - 1] + 1);
    }
    __syncthreads();

    if (i < N_NODES) {
        int ex = prefix_sh + s[t] - v;   // exclusive prefix
        rowptr[i] = ex;
        cursor[i] = ex;
    }
    if (b == 0 && t == 0) rowptr[N_NODES] = N_EDGES;
}

__global__ void csr_fill(const void* __restrict__ ei, int* __restrict__ cursor,
                         int* __restrict__ csr) {
    int is64 = detect64(ei);
    int e = blockIdx.x * blockDim.x + threadIdx.x;
    if (e >= N_EDGES) return;
    int s = idx_at(ei, e, is64);
    int d = idx_at(ei, (long long)N_EDGES + e, is64);
    int p = atomicAdd(&cursor[d], 1);
    csr[p] = s;
}

// ---------------- aggregation: out[i] = h[i] + sum_{j in N(i)} h[j] ----------
// (R5 form - measured best) float4 lanes; C/4 threads per node.
__global__ void aggregate4(const float4* __restrict__ h4,
                           const int* __restrict__ rowptr,
                           const int* __restrict__ csr,
                           float4* __restrict__ out,
                           int c4shift)            // log2(C/4): 5 or 6
{
    int c4 = 1 << c4shift;
    int sub  = threadIdx.x >> c4shift;
    int t    = threadIdx.x & (c4 - 1);
    int npb  = 256 >> c4shift;
    int node = blockIdx.x * npb + sub;
    if (node >= N_NODES) return;

    int beg = rowptr[node], end = rowptr[node + 1];
    float4 acc = h4[((size_t)node << c4shift) + t];
    int e = beg;
    for (; e + 4 <= end; e += 4) {
        int s0 = csr[e], s1 = csr[e + 1], s2 = csr[e + 2], s3 = csr[e + 3];
        float4 v0 = h4[((size_t)s0 << c4shift) + t];
        float4 v1 = h4[((size_t)s1 << c4shift) + t];
        float4 v2 = h4[((size_t)s2 << c4shift) + t];
        float4 v3 = h4[((size_t)s3 << c4shift) + t];
        acc.x += v0.x + v1.x + v2.x + v3.x;
        acc.y += v0.y + v1.y + v2.y + v3.y;
        acc.z += v0.z + v1.z + v2.z + v3.z;
        acc.w += v0.w + v1.w + v2.w + v3.w;
    }
    for (; e < end; e++) {
        float4 v = h4[((size_t)csr[e] << c4shift) + t];
        acc.x += v.x; acc.y += v.y; acc.z += v.z; acc.w += v.w;
    }
    out[((size_t)node << c4shift) + t] = acc;
}

// ---------------- TF32 tensor-core GEMM (R5 form - measured best) -------------
#define GBM 128
#define GBN 128
#define GBK 32
#define ASTRIDE 36
#define BSTRIDE 136

__device__ __forceinline__ uint32_t f2tf32(float f) {
    uint32_t r;
    asm("cvt.rna.tf32.f32 %0, %1;" : "=r"(r) : "f"(f));
    return r;
}

__global__ __launch_bounds__(256, 2)
void gemm_tf32(const float* __restrict__ A,
               const float* __restrict__ W,      // K x N row-major
               const float* __restrict__ bias,   // N
               float* __restrict__ C,
               int M, int K, int N)
{
    __shared__ uint32_t As[GBM][ASTRIDE];
    __shared__ uint32_t Bs[GBK][BSTRIDE];

    int bm = blockIdx.x * GBM;
    int bn = blockIdx.y * GBN;
    int tid  = threadIdx.x;
    int wid  = tid >> 5;
    int lane = tid & 31;
    int grp  = lane >> 2;     // 0..7
    int tig  = lane & 3;      // 0..3
    int wm = (wid & 3) * 32;  // warp row offset in tile
    int wn = (wid >> 2) * 64; // warp col offset in tile

    float acc[2][8][4];
    #pragma unroll
    for (int i = 0; i < 2; i++)
        #pragma unroll
        for (int j = 0; j < 8; j++)
            #pragma unroll
            for (int r = 0; r < 4; r++) acc[i][j][r] = 0.f;

    float4 pa[4], pb[4];

    auto ld_tiles = [&](int k0) {
        #pragma unroll
        for (int i = 0; i < 4; i++) {
            int li = tid + i * 256;
            int r  = li >> 3;          // 0..127
            int cq = (li & 7) * 4;     // 0..28
            int row = bm + r;
            pa[i] = (row < M) ? *(const float4*)(A + (size_t)row * K + k0 + cq)
                              : make_float4(0.f, 0.f, 0.f, 0.f);
        }
        #pragma unroll
        for (int i = 0; i < 4; i++) {
            int li = tid + i * 256;
            int kr = li >> 5;          // 0..31
            int cq = (li & 31) * 4;    // 0..124
            pb[i] = *(const float4*)(W + (size_t)(k0 + kr) * N + bn + cq);
        }
    };

    auto st_tiles = [&]() {
        #pragma unroll
        for (int i = 0; i < 4; i++) {
            int li = tid + i * 256;
            int r  = li >> 3;
            int cq = (li & 7) * 4;
            As[r][cq + 0] = f2tf32(pa[i].x);
            As[r][cq + 1] = f2tf32(pa[i].y);
            As[r][cq + 2] = f2tf32(pa[i].z);
            As[r][cq + 3] = f2tf32(pa[i].w);
        }
        #pragma unroll
        for (int i = 0; i < 4; i++) {
            int li = tid + i * 256;
            int kr = li >> 5;
            int cq = (li & 31) * 4;
            Bs[kr][cq + 0] = f2tf32(pb[i].x);
            Bs[kr][cq + 1] = f2tf32(pb[i].y);
            Bs[kr][cq + 2] = f2tf32(pb[i].z);
            Bs[kr][cq + 3] = f2tf32(pb[i].w);
        }
    };

    ld_tiles(0);

    for (int k0 = 0; k0 < K; k0 += GBK) {
        st_tiles();
        __syncthreads();
        if (k0 + GBK < K) ld_tiles(k0 + GBK);   // hide LDG behind MMA phase

        #pragma unroll
        for (int ks = 0; ks < GBK; ks += 8) {
            uint32_t af[2][4];
            #pragma unroll
            for (int mt = 0; mt < 2; mt++) {
                int r0 = wm + mt * 16 + grp;
                af[mt][0] = As[r0][ks + tig];
                af[mt][1] = As[r0 + 8][ks + tig];
                af[mt][2] = As[r0][ks + tig + 4];
                af[mt][3] = As[r0 + 8][ks + tig + 4];
            }
            uint32_t bf[8][2];
            #pragma unroll
            for (int nt = 0; nt < 8; nt++) {
                int c0 = wn + nt * 8 + grp;
                bf[nt][0] = Bs[ks + tig][c0];
                bf[nt][1] = Bs[ks + tig + 4][c0];
            }
            #pragma unroll
            for (int mt = 0; mt < 2; mt++)
                #pragma unroll
                for (int nt = 0; nt < 8; nt++) {
                    asm volatile(
                        "mma.sync.aligned.m16n8k8.row.col.f32.tf32.tf32.f32 "
                        "{%0,%1,%2,%3}, {%4,%5,%6,%7}, {%8,%9}, {%0,%1,%2,%3};"
                        : "+f"(acc[mt][nt][0]), "+f"(acc[mt][nt][1]),
                          "+f"(acc[mt][nt][2]), "+f"(acc[mt][nt][3])
                        : "r"(af[mt][0]), "r"(af[mt][1]),
                          "r"(af[mt][2]), "r"(af[mt][3]),
                          "r"(bf[nt][0]), "r"(bf[nt][1]));
                }
        }
        __syncthreads();
    }

    // epilogue: bias + relu, float2 stores
    #pragma unroll
    for (int mt = 0; mt < 2; mt++) {
        #pragma unroll
        for (int nt = 0; nt < 8; nt++) {
            int col = bn + wn + nt * 8 + 2 * tig;
            float b0 = bias[col], b1 = bias[col + 1];
            int r0 = bm + wm + mt * 16 + grp;
            if (r0 < M) {
                float2 c;
                c.x = fmaxf(acc[mt][nt][0] + b0, 0.f);
                c.y = fmaxf(acc[mt][nt][1] + b1, 0.f);
                *(float2*)(C + (size_t)r0 * N + col) = c;
            }
            if (r0 + 8 < M) {
                float2 c;
                c.x = fmaxf(acc[mt][nt][2] + b0, 0.f);
                c.y = fmaxf(acc[mt][nt][3] + b1, 0.f);
                *(float2*)(C + (size_t)(r0 + 8) * N + col) = c;
            }
        }
    }
}

// ---------------- pooling over sorted batch -----------------------------------
__global__ void graph_bounds(const void* __restrict__ batch,
                             const void* __restrict__ ei,
                             int* __restrict__ gstart) {
    int is64 = detect64(ei);   // detect from ei (random values; batch starts at 0)
    int g = blockIdx.x * blockDim.x + threadIdx.x;
    if (g > N_GRAPHS) return;
    int lo = 0, hi = N_NODES;
    while (lo < hi) {
        int mid = (lo + hi) >> 1;
        if (idx_at(batch, mid, is64) < g) lo = mid + 1; else hi = mid;
    }
    gstart[g] = lo;
}

__global__ void pool_mean(const float* __restrict__ h,
                          const int* __restrict__ gstart,
                          float* __restrict__ pooled) {
    int g = blockIdx.x;
    int t = threadIdx.x;           // HID threads
    int beg = gstart[g], end = gstart[g + 1];
    float acc = 0.f;
    int n = beg;
    for (; n + 4 <= end; n += 4) {
        float a0 = h[(size_t)(n + 0) * HID + t];
        float a1 = h[(size_t)(n + 1) * HID + t];
        float a2 = h[(size_t)(n + 2) * HID + t];
        float a3 = h[(size_t)(n + 3) * HID + t];
        acc += a0 + a1 + a2 + a3;
    }
    for (; n < end; n++) acc += h[(size_t)n * HID + t];
    float c = fmaxf((float)(end - beg), 1.0f);
    pooled[(size_t)g * HID + t] = acc / c;
}

// ---------------- final MLP: out = relu(pooled@W1+b1)@W2+b2 ------------------
__global__ void final_mlp(const float* __restrict__ pooled,
                          const float* __restrict__ w1, const float* __restrict__ b1,
                          const float* __restrict__ w2, const float* __restrict__ b2,
                          float* __restrict__ out) {
    __shared__ float p[HID];
    __shared__ float hh[HID];
    int g = blockIdx.x;
    int t = threadIdx.x;

    p[t] = pooled[(size_t)g * HID + t];
    __syncthreads();

    float acc = b1[t];
    #pragma unroll 8
    for (int k = 0; k < HID; k++)
        acc += p[k] * w1[(size_t)k * HID + t];
    hh[t] = fmaxf(acc, 0.f);
    __syncthreads();

    int o  = t >> 4;
    int kk = t & 15;
    float s = 0.f;
    for (int k = kk; k < HID; k += 16)
        s += hh[k] * w2[(size_t)k * OUT_C + o];
    #pragma unroll
    for (int off = 8; off; off >>= 1)
        s += __shfl_xor_sync(0xffffffffu, s, off);
    if (kk == 0) out[(size_t)g * OUT_C + o] = s + b2[o];
}

// ---------------- launcher ----------------------------------------------------
extern "C" void kernel_launch(void* const* d_in, const int* in_sizes, int n_in,
                              void* d_out, int out_size)
{
    const float* x     = (const float*)d_in[0];
    const void*  ei    = d_in[1];
    const void*  batch = d_in[2];
    const float* w[16];
    for (int i = 0; i < 16; i++) w[i] = (const float*)d_in[3 + i];
    float* out = (float*)d_out;

    float *agg, *tmp, *h, *pool;
    int *deg, *rowptr, *cursor, *csr, *gstart, *chain, *arrive;
    cudaGetSymbolAddress((void**)&agg,    g_agg);
    cudaGetSymbolAddress((void**)&tmp,    g_tmp);
    cudaGetSymbolAddress((void**)&h,      g_h);
    cudaGetSymbolAddress((void**)&pool,   g_pool);
    cudaGetSymbolAddress((void**)&deg,    g_deg);
    cudaGetSymbolAddress((void**)&rowptr, g_rowptr);
    cudaGetSymbolAddress((void**)&cursor, g_cursor);
    cudaGetSymbolAddress((void**)&csr,    g_csr);
    cudaGetSymbolAddress((void**)&gstart, g_gstart);
    cudaGetSymbolAddress((void**)&chain,  g_chain);
    cudaGetSymbolAddress((void**)&arrive, g_arrive);

    // ---- CSR build (2 kernels; reused by all 3 layers) ----
    cudaMemsetAsync(deg, 0, N_NODES * sizeof(int));
    cudaMemsetAsync(chain, 0, sizeof(g_chain));
    cudaMemsetAsync(arrive, 0, sizeof(int));
    hist_scan<<<SCAN_NB, SCAN_B>>>(ei, deg, rowptr, cursor);        // launch 0
    csr_fill<<<(N_EDGES + 255) / 256, 256>>>(ei, cursor, csr);      // launch 1

    // ---- 3 GIN layers ----
    for (int layer = 0; layer < 3; layer++) {
        const float* hin = (layer == 0) ? x : h;
        int K = (layer == 0) ? IN_C : HID;
        int c4shift = (layer == 0) ? 5 : 6;
        int npb = 256 >> c4shift;

        aggregate4<<<(N_NODES + npb - 1) / npb, 256>>>(             // launch 2 (L0)
            (const float4*)hin, rowptr, csr, (float4*)agg, c4shift);

        dim3 grid((N_NODES + GBM - 1) / GBM, HID / GBN);
        gemm_tf32<<<grid, 256>>>(agg, w[layer * 4 + 0], w[layer * 4 + 1],
                                 tmp, N_NODES, K, HID);             // launch 3 (L0)
        gemm_tf32<<<grid, 256>>>(tmp, w[layer * 4 + 2], w[layer * 4 + 3],
                                 h, N_NODES, HID, HID);
    }

    // ---- pooling (batch is sorted) ----
    graph_bounds<<<3, 256>>>(batch, ei, gstart);
    pool_mean<<<N_GRAPHS, HID>>>(h, gstart, pool);

    final_mlp<<<N_GRAPHS, HID>>>(pool, w[12], w[13], w[14], w[15], out);
}

// round 8
// speedup vs baseline: 1.1527x; 1.0516x over previous
#include <cuda_runtime.h>
#include <cuda_bf16.h>
#include <cstdint>

#define N_NODES  50000
#define N_EDGES  800000
#define N_GRAPHS 512
#define IN_C     128
#define HID      256
#define OUT_C    16

// ---------------- scratch (static device globals; no allocation) -------------
__device__ float g_agg [(size_t)N_NODES * HID];
__device__ float g_tmp [(size_t)N_NODES * HID];
__device__ float g_h   [(size_t)N_NODES * HID];
__device__ float g_pool[N_GRAPHS * HID];
// transposed tf32 weights: layout [N][K] per matrix
// offsets: m0:128*256=32768, then 5 x 256*256
#define WT_TOTAL (32768 + 5 * 65536)
__device__ float g_wt [WT_TOTAL];
__device__ int   g_deg   [N_NODES];
__device__ int   g_ex    [N_NODES];
__device__ int   g_bsums [128];
__device__ int   g_rowptr[N_NODES + 1];
__device__ int   g_cursor[N_NODES];
__device__ int   g_csr   [N_EDGES];
__device__ int   g_gstart[N_GRAPHS + 1];

// ---------------- helpers -----------------------------------------------------
__device__ __forceinline__ int detect64(const void* ei) {
    const unsigned int* w = (const unsigned int*)ei;
    return ((w[1] | w[3] | w[5] | w[7]) == 0u) ? 1 : 0;
}
__device__ __forceinline__ int idx_at(const void* p, long long i, int is64) {
    if (is64) return (int)((const long long*)p)[i];
    return ((const int*)p)[i];
}
__device__ __forceinline__ uint32_t f2tf32(float f) {
    uint32_t r;
    asm("cvt.rna.tf32.f32 %0, %1;" : "=r"(r) : "f"(f));
    return r;
}
__device__ __forceinline__ float rtf(float f) {
    return __uint_as_float(f2tf32(f));
}

// ---------------- weight pre-convert: W[K][N] f32 -> Wt[N][K] tf32 ------------
__global__ void wconv(const float* __restrict__ w0, const float* __restrict__ w1,
                      const float* __restrict__ w2, const float* __restrict__ w3,
                      const float* __restrict__ w4, const float* __restrict__ w5,
                      float* __restrict__ dst) {
    int idx = blockIdx.x * blockDim.x + threadIdx.x;
    if (idx >= WT_TOTAL) return;
    const float* src;
    int base, K;
    if (idx < 32768)        { src = w0; base = 0;      K = 128; }
    else if (idx < 98304)   { src = w1; base = 32768;  K = 256; }
    else if (idx < 163840)  { src = w2; base = 98304;  K = 256; }
    else if (idx < 229376)  { src = w3; base = 163840; K = 256; }
    else if (idx < 294912)  { src = w4; base = 229376; K = 256; }
    else                    { src = w5; base = 294912; K = 256; }
    int o = idx - base;
    int n = o / K, k = o % K;
    dst[idx] = rtf(src[(size_t)k * HID + n]);
}

// ---------------- CSR build (R5 split form — measured best) --------------------
__global__ void deg_hist(const void* __restrict__ ei, int* __restrict__ deg) {
    int is64 = detect64(ei);
    int e = blockIdx.x * blockDim.x + threadIdx.x;
    if (e >= N_EDGES) return;
    int d = idx_at(ei, (long long)N_EDGES + e, is64);
    atomicAdd(&deg[d], 1);
}

#define SCAN_B 512
__global__ void scan1(const int* __restrict__ deg, int* __restrict__ ex,
                      int* __restrict__ sums) {
    __shared__ int s[SCAN_B];
    int b = blockIdx.x, t = threadIdx.x;
    int i = b * SCAN_B + t;
    int v = (i < N_NODES) ? deg[i] : 0;
    s[t] = v; __syncthreads();
    for (int off = 1; off < SCAN_B; off <<= 1) {
        int x = (t >= off) ? s[t - off] : 0;
        __syncthreads();
        s[t] += x;
        __syncthreads();
    }
    if (i < N_NODES) ex[i] = s[t] - v;
    if (t == SCAN_B - 1) sums[b] = s[t];
}

__global__ void scan2(int* __restrict__ sums, int nb) {
    __shared__ int s[128];
    int t = threadIdx.x;
    int v = (t < nb) ? sums[t] : 0;
    s[t] = v; __syncthreads();
    for (int off = 1; off < 128; off <<= 1) {
        int x = (t >= off) ? s[t - off] : 0;
        __syncthreads();
        s[t] += x;
        __syncthreads();
    }
    if (t < nb) sums[t] = s[t] - v;
}

__global__ void scan3(const int* __restrict__ ex, const int* __restrict__ sums,
                      int* __restrict__ rowptr, int* __restrict__ cursor) {
    int i = blockIdx.x * blockDim.x + threadIdx.x;
    if (i < N_NODES) {
        int v = ex[i] + sums[i >> 9];
        rowptr[i] = v;
        cursor[i] = v;
    }
    if (i == 0) rowptr[N_NODES] = N_EDGES;
}

__global__ void csr_fill(const void* __restrict__ ei, int* __restrict__ cursor,
                         int* __restrict__ csr) {
    int is64 = detect64(ei);
    int e = blockIdx.x * blockDim.x + threadIdx.x;
    if (e >= N_EDGES) return;
    int s = idx_at(ei, e, is64);
    int d = idx_at(ei, (long long)N_EDGES + e, is64);
    int p = atomicAdd(&cursor[d], 1);
    csr[p] = s;
}

// ---------------- aggregation: out[i] = tf32(h[i] + sum_{j in N(i)} h[j]) -----
// (R5 form) float4 lanes; C/4 threads per node; output rounded to tf32 since
// it feeds the cp.async GEMM directly.
__global__ void aggregate4(const float4* __restrict__ h4,
                           const int* __restrict__ rowptr,
                           const int* __restrict__ csr,
                           float4* __restrict__ out,
                           int c4shift)            // log2(C/4): 5 or 6
{
    int c4 = 1 << c4shift;
    int sub  = threadIdx.x >> c4shift;
    int t    = threadIdx.x & (c4 - 1);
    int npb  = 256 >> c4shift;
    int node = blockIdx.x * npb + sub;
    if (node >= N_NODES) return;

    int beg = rowptr[node], end = rowptr[node + 1];
    float4 acc = h4[((size_t)node << c4shift) + t];
    int e = beg;
    for (; e + 4 <= end; e += 4) {
        int s0 = csr[e], s1 = csr[e + 1], s2 = csr[e + 2], s3 = csr[e + 3];
        float4 v0 = h4[((size_t)s0 << c4shift) + t];
        float4 v1 = h4[((size_t)s1 << c4shift) + t];
        float4 v2 = h4[((size_t)s2 << c4shift) + t];
        float4 v3 = h4[((size_t)s3 << c4shift) + t];
        acc.x += v0.x + v1.x + v2.x + v3.x;
        acc.y += v0.y + v1.y + v2.y + v3.y;
        acc.z += v0.z + v1.z + v2.z + v3.z;
        acc.w += v0.w + v1.w + v2.w + v3.w;
    }
    for (; e < end; e++) {
        float4 v = h4[((size_t)csr[e] << c4shift) + t];
        acc.x += v.x; acc.y += v.y; acc.z += v.z; acc.w += v.w;
    }
    float4 r;
    r.x = rtf(acc.x); r.y = rtf(acc.y); r.z = rtf(acc.z); r.w = rtf(acc.w);
    out[((size_t)node << c4shift) + t] = r;
}

// ---------------- TF32 tensor GEMM, cp.async double-buffered ------------------
// A: [M][K] f32 already tf32-rounded. Wt: [N][K] tf32. C = relu(A@W + bias),
// optionally re-rounded to tf32 (when C feeds the next GEMM).
// BM=BN=128, BK=16, 256 threads (8 warps: 4m x 2n), warp tile 32x64.
// Stage = As[128][20] + Bt[128][20] words; 2 stages = 40 KB static smem.
#define GBM 128
#define GBN 128
#define GBK 16
#define TSTR 20                 // row stride in words (conflict-free: 20%32=20)
#define STAGE_W (2 * 128 * TSTR)   // words per stage (A then B)

__global__ __launch_bounds__(256, 2)
void gemm_tf32(const float* __restrict__ A,
               const float* __restrict__ Wt,     // [N][K] tf32
               const float* __restrict__ bias,   // N, f32
               float* __restrict__ C,
               int M, int K, int N, int doRound)
{
    __shared__ uint32_t Sm[2 * STAGE_W];

    uint32_t smem_base;
    asm("{ .reg .u64 tmp; cvta.to.shared.u64 tmp, %1; cvt.u32.u64 %0, tmp; }"
        : "=r"(smem_base) : "l"(Sm));

    int bm = blockIdx.x * GBM;
    int bn = blockIdx.y * GBN;
    int tid  = threadIdx.x;
    int wid  = tid >> 5;
    int lane = tid & 31;
    int grp  = lane >> 2;     // 0..7
    int tig  = lane & 3;      // 0..3
    int wm = (wid & 3) * 32;  // warp row offset
    int wn = (wid >> 2) * 64; // warp col offset

    float acc[2][8][4];
    #pragma unroll
    for (int i = 0; i < 2; i++)
        #pragma unroll
        for (int j = 0; j < 8; j++)
            #pragma unroll
            for (int r = 0; r < 4; r++) acc[i][j][r] = 0.f;

    // per-thread fixed chunk coords (chunk = 16B = 4 floats)
    // A: 128 rows x 4 chunks; thread handles chunks tid, tid+256
    auto cp_tile = [&](int k0, int buf) {
        uint32_t sa = smem_base + (uint32_t)buf * (STAGE_W * 4);
        uint32_t sb = sa + 128 * TSTR * 4;
        #pragma unroll
        for (int i = 0; i < 2; i++) {
            int c = tid + i * 256;
            int r = c >> 2, kq = (c & 3) * 4;
            const float* src = A + (size_t)(bm + r) * K + k0 + kq;
            int vbytes = (bm + r < M) ? 16 : 0;
            asm volatile("cp.async.cg.shared.global [%0], [%1], 16, %2;"
                :: "r"(sa + (uint32_t)(r * TSTR + kq) * 4), "l"(src), "r"(vbytes)
                : "memory");
        }
        #pragma unroll
        for (int i = 0; i < 2; i++) {
            int c = tid + i * 256;
            int n = c >> 2, kq = (c & 3) * 4;
            const float* src = Wt + (size_t)(bn + n) * K + k0 + kq;
            asm volatile("cp.async.cg.shared.global [%0], [%1], 16, %2;"
                :: "r"(sb + (uint32_t)(n * TSTR + kq) * 4), "l"(src), "r"(16)
                : "memory");
        }
        asm volatile("cp.async.commit_group;" ::: "memory");
    };

    cp_tile(0, 0);
    int niter = K / GBK;

    for (int it = 0; it < niter; it++) {
        asm volatile("cp.async.wait_group 0;" ::: "memory");
        __syncthreads();
        if (it + 1 < niter) cp_tile((it + 1) * GBK, (it + 1) & 1);

        const uint32_t* Asb = Sm + (it & 1) * STAGE_W;
        const uint32_t* Btb = Asb + 128 * TSTR;

        #pragma unroll
        for (int ks = 0; ks < GBK; ks += 8) {
            uint32_t af[2][4];
            #pragma unroll
            for (int mt = 0; mt < 2; mt++) {
                int r0 = wm + mt * 16 + grp;
                af[mt][0] = Asb[r0 * TSTR + ks + tig];
                af[mt][1] = Asb[(r0 + 8) * TSTR + ks + tig];
                af[mt][2] = Asb[r0 * TSTR + ks + tig + 4];
                af[mt][3] = Asb[(r0 + 8) * TSTR + ks + tig + 4];
            }
            uint32_t bf[8][2];
            #pragma unroll
            for (int nt = 0; nt < 8; nt++) {
                int c0 = wn + nt * 8 + grp;
                bf[nt][0] = Btb[c0 * TSTR + ks + tig];
                bf[nt][1] = Btb[c0 * TSTR + ks + tig + 4];
            }
            #pragma unroll
            for (int mt = 0; mt < 2; mt++)
                #pragma unroll
                for (int nt = 0; nt < 8; nt++) {
                    asm volatile(
                        "mma.sync.aligned.m16n8k8.row.col.f32.tf32.tf32.f32 "
                        "{%0,%1,%2,%3}, {%4,%5,%6,%7}, {%8,%9}, {%0,%1,%2,%3};"
                        : "+f"(acc[mt][nt][0]), "+f"(acc[mt][nt][1]),
                          "+f"(acc[mt][nt][2]), "+f"(acc[mt][nt][3])
                        : "r"(af[mt][0]), "r"(af[mt][1]),
                          "r"(af[mt][2]), "r"(af[mt][3]),
                          "r"(bf[nt][0]), "r"(bf[nt][1]));
                }
        }
        __syncthreads();
    }

    // epilogue: bias + relu (+ tf32 round), float2 stores
    #pragma unroll
    for (int mt = 0; mt < 2; mt++) {
        #pragma unroll
        for (int nt = 0; nt < 8; nt++) {
            int col = bn + wn + nt * 8 + 2 * tig;
            float b0 = bias[col], b1 = bias[col + 1];
            int r0 = bm + wm + mt * 16 + grp;
            float v00 = fmaxf(acc[mt][nt][0] + b0, 0.f);
            float v01 = fmaxf(acc[mt][nt][1] + b1, 0.f);
            float v10 = fmaxf(acc[mt][nt][2] + b0, 0.f);
            float v11 = fmaxf(acc[mt][nt][3] + b1, 0.f);
            if (doRound) {
                v00 = rtf(v00); v01 = rtf(v01);
                v10 = rtf(v10); v11 = rtf(v11);
            }
            if (r0 < M)
                *(float2*)(C + (size_t)r0 * N + col) = make_float2(v00, v01);
            if (r0 + 8 < M)
                *(float2*)(C + (size_t)(r0 + 8) * N + col) = make_float2(v10, v11);
        }
    }
}

// ---------------- pooling over sorted batch -----------------------------------
__global__ void graph_bounds(const void* __restrict__ batch,
                             const void* __restrict__ ei,
                             int* __restrict__ gstart) {
    int is64 = detect64(ei);
    int g = blockIdx.x * blockDim.x + threadIdx.x;
    if (g > N_GRAPHS) return;
    int lo = 0, hi = N_NODES;
    while (lo < hi) {
        int mid = (lo + hi) >> 1;
        if (idx_at(batch, mid, is64) < g) lo = mid + 1; else hi = mid;
    }
    gstart[g] = lo;
}

__global__ void pool_mean(const float* __restrict__ h,
                          const int* __restrict__ gstart,
                          float* __restrict__ pooled) {
    int g = blockIdx.x;
    int t = threadIdx.x;           // HID threads
    int beg = gstart[g], end = gstart[g + 1];
    float acc = 0.f;
    int n = beg;
    for (; n + 4 <= end; n += 4) {
        float a0 = h[(size_t)(n + 0) * HID + t];
        float a1 = h[(size_t)(n + 1) * HID + t];
        float a2 = h[(size_t)(n + 2) * HID + t];
        float a3 = h[(size_t)(n + 3) * HID + t];
        acc += a0 + a1 + a2 + a3;
    }
    for (; n < end; n++) acc += h[(size_t)n * HID + t];
    float c = fmaxf((float)(end - beg), 1.0f);
    pooled[(size_t)g * HID + t] = acc / c;
}

// ---------------- final MLP: out = relu(pooled@W1+b1)@W2+b2 ------------------
__global__ void final_mlp(const float* __restrict__ pooled,
                          const float* __restrict__ w1, const float* __restrict__ b1,
                          const float* __restrict__ w2, const float* __restrict__ b2,
                          float* __restrict__ out) {
    __shared__ float p[HID];
    __shared__ float hh[HID];
    int g = blockIdx.x;
    int t = threadIdx.x;

    p[t] = pooled[(size_t)g * HID + t];
    __syncthreads();

    float acc = b1[t];
    #pragma unroll 8
    for (int k = 0; k < HID; k++)
        acc += p[k] * w1[(size_t)k * HID + t];
    hh[t] = fmaxf(acc, 0.f);
    __syncthreads();

    int o  = t >> 4;
    int kk = t & 15;
    float s = 0.f;
    for (int k = kk; k < HID; k += 16)
        s += hh[k] * w2[(size_t)k * OUT_C + o];
    #pragma unroll
    for (int off = 8; off; off >>= 1)
        s += __shfl_xor_sync(0xffffffffu, s, off);
    if (kk == 0) out[(size_t)g * OUT_C + o] = s + b2[o];
}

// ---------------- launcher ----------------------------------------------------
extern "C" void kernel_launch(void* const* d_in, const int* in_sizes, int n_in,
                              void* d_out, int out_size)
{
    const float* x     = (const float*)d_in[0];
    const void*  ei    = d_in[1];
    const void*  batch = d_in[2];
    const float* w[16];
    for (int i = 0; i < 16; i++) w[i] = (const float*)d_in[3 + i];
    float* out = (float*)d_out;

    float *agg, *tmp, *h, *pool, *wt;
    int *deg, *ex, *bsums, *rowptr, *cursor, *csr, *gstart;
    cudaGetSymbolAddress((void**)&agg,    g_agg);
    cudaGetSymbolAddress((void**)&tmp,    g_tmp);
    cudaGetSymbolAddress((void**)&h,      g_h);
    cudaGetSymbolAddress((void**)&pool,   g_pool);
    cudaGetSymbolAddress((void**)&wt,     g_wt);
    cudaGetSymbolAddress((void**)&deg,    g_deg);
    cudaGetSymbolAddress((void**)&ex,     g_ex);
    cudaGetSymbolAddress((void**)&bsums,  g_bsums);
    cudaGetSymbolAddress((void**)&rowptr, g_rowptr);
    cudaGetSymbolAddress((void**)&cursor, g_cursor);
    cudaGetSymbolAddress((void**)&csr,    g_csr);
    cudaGetSymbolAddress((void**)&gstart, g_gstart);

    // weight offsets in g_wt ([N][K] each)
    const int wt_off[6] = {0, 32768, 98304, 163840, 229376, 294912};

    // ---- weight pre-convert (tf32 + transpose) ----
    wconv<<<(WT_TOTAL + 255) / 256, 256>>>(w[0], w[2], w[4], w[6], w[8], w[10], wt);

    // ---- CSR build (once, reused by all 3 layers) ----
    cudaMemsetAsync(deg, 0, N_NODES * sizeof(int));
    deg_hist<<<(N_EDGES + 255) / 256, 256>>>(ei, deg);
    int nb = (N_NODES + SCAN_B - 1) / SCAN_B;   // 98
    scan1<<<nb, SCAN_B>>>(deg, ex, bsums);
    scan2<<<1, 128>>>(bsums, nb);
    scan3<<<(N_NODES + 256) / 256, 256>>>(ex, bsums, rowptr, cursor);
    csr_fill<<<(N_EDGES + 255) / 256, 256>>>(ei, cursor, csr);

    // ---- 3 GIN layers ----
    for (int layer = 0; layer < 3; layer++) {
        const float* hin = (layer == 0) ? x : h;
        int K = (layer == 0) ? IN_C : HID;
        int c4shift = (layer == 0) ? 5 : 6;
        int npb = 256 >> c4shift;

        aggregate4<<<(N_NODES + npb - 1) / npb, 256>>>(
            (const float4*)hin, rowptr, csr, (float4*)agg, c4shift);

        dim3 grid((N_NODES + GBM - 1) / GBM, HID / GBN);
        // gemm1: A=agg (tf32-rounded), output tmp rounded (feeds gemm2)
        gemm_tf32<<<grid, 256>>>(agg, wt + wt_off[layer * 2 + 0],
                                 w[layer * 4 + 1], tmp, N_NODES, K, HID, 1);
        // gemm2: A=tmp (rounded), output h full f32 (feeds agg/pool)
        gemm_tf32<<<grid, 256>>>(tmp, wt + wt_off[layer * 2 + 1],
                                 w[layer * 4 + 3], h, N_NODES, HID, HID, 0);
    }

    // ---- pooling (batch is sorted) ----
    graph_bounds<<<3, 256>>>(batch, ei, gstart);
    pool_mean<<<N_GRAPHS, HID>>>(h, gstart, pool);

    final_mlp<<<N_GRAPHS, HID>>>(pool, w[12], w[13], w[14], w[15], out);
}